// round 3
// baseline (speedup 1.0000x reference)
#include <cuda_runtime.h>
#include <cstdint>

#define B_TOT   4096
#define NM      25
#define C_CH    64
#define CP      (C_CH / 2)        /* 32 float2 channel-pairs, one per lane */
#define NNZ_K   1000
#define NW      55
#define THREADS 256
#define WARPS   8
#define EPW     (NNZ_K / WARPS)   /* 125 entries per warp */

// Packed per-entry metadata: {M1 | M2<<5 | l_ind<<10 | M_out<<16, cg_bits}
__device__ uint2 g_meta[NNZ_K];

__global__ void pack_kernel(const int* __restrict__ Mo, const int* __restrict__ M1,
                            const int* __restrict__ M2, const int* __restrict__ li,
                            const float* __restrict__ cg) {
    int n = blockIdx.x * blockDim.x + threadIdx.x;
    if (n < NNZ_K) {
        unsigned p = (unsigned)M1[n] | ((unsigned)M2[n] << 5) |
                     ((unsigned)li[n] << 10) | ((unsigned)Mo[n] << 16);
        g_meta[n] = make_uint2(p, __float_as_uint(cg[n]));
    }
}

__global__ void __launch_bounds__(THREADS) tp_kernel(
    const float* __restrict__ x1, const float* __restrict__ x2,
    const float* __restrict__ wt, float* __restrict__ out)
{
    __shared__ float2 s_x1 [NM * CP];
    __shared__ float2 s_x2 [NM * CP];
    __shared__ float2 s_w  [NW * CP];
    __shared__ float2 s_acc[NM * CP];
    __shared__ float2 s_pv [WARPS * 2 * CP];   // boundary-partial values
    __shared__ uint2  s_meta[NNZ_K];
    __shared__ int    s_pmo[WARPS * 2];        // boundary-partial segment ids

    const int tid = threadIdx.x;
    const int b   = blockIdx.x;

    // ---- stage batch data into shared (float2 granularity) ----
    const float2* gx1 = (const float2*)(x1 + (size_t)b * NM * C_CH);
    const float2* gx2 = (const float2*)(x2 + (size_t)b * NM * C_CH);
    const float2* gw  = (const float2*)(wt + (size_t)b * NW * C_CH);
    for (int i = tid; i < NM * CP; i += THREADS) {
        s_x1[i] = gx1[i];
        s_x2[i] = gx2[i];
        s_acc[i] = make_float2(0.f, 0.f);
    }
    for (int i = tid; i < NW * CP; i += THREADS) s_w[i] = gw[i];
    for (int i = tid; i < WARPS * 2 * CP; i += THREADS) s_pv[i] = make_float2(0.f, 0.f);
    if (tid < WARPS * 2) s_pmo[tid] = 0;
    for (int i = tid; i < NNZ_K; i += THREADS) s_meta[i] = g_meta[i];
    __syncthreads();

    const int lane = tid & 31;
    const int w    = tid >> 5;

    // ---- main loop: warp w handles entries [w*EPW, (w+1)*EPW), all 64 channels ----
    int n = w * EPW;
    const int nend = n + EPW;
    int cur = (int)(s_meta[n].x >> 16);
    float2 acc = make_float2(0.f, 0.f);
    bool first = true;

    #pragma unroll 4
    for (; n < nend; ++n) {
        const uint2 me = s_meta[n];        // uniform broadcast (1 wavefront)
        const unsigned p = me.x;
        const int mo = (int)(p >> 16);
        if (mo != cur) {                   // uniform branch: close segment `cur`
            if (first) {                   // first segment may span a warp boundary -> partial slot
                s_pv[(w * 2) * CP + lane] = acc;
                if (lane == 0) s_pmo[w * 2] = cur;
                first = false;
            } else {                       // interior segment: exclusively owned (M_out sorted)
                s_acc[cur * CP + lane] = acc;
            }
            acc = make_float2(0.f, 0.f);
            cur = mo;
        }
        const float2 v1 = s_x1[(p & 31u)         * CP + lane];
        const float2 v2 = s_x2[((p >> 5)  & 31u) * CP + lane];
        const float2 vw = s_w [((p >> 10) & 63u) * CP + lane];
        const float  cg = __uint_as_float(me.y);
        acc.x = fmaf(v1.x * v2.x, cg * vw.x, acc.x);
        acc.y = fmaf(v1.y * v2.y, cg * vw.y, acc.y);
    }
    // final (possibly boundary-spanning) segment -> partial slot
    s_pv[(w * 2 + 1) * CP + lane] = acc;
    if (lane == 0) s_pmo[w * 2 + 1] = cur;
    __syncthreads();

    // ---- merge boundary partials: one warp, lane owns its channel pair -> no races ----
    if (tid < 32) {
        #pragma unroll
        for (int s = 0; s < WARPS * 2; ++s) {
            const int mo = s_pmo[s];
            const float2 v = s_pv[s * CP + lane];
            float2 a = s_acc[mo * CP + lane];
            a.x += v.x; a.y += v.y;
            s_acc[mo * CP + lane] = a;
        }
    }
    __syncthreads();

    // ---- write out ----
    float2* go = (float2*)(out + (size_t)b * NM * C_CH);
    for (int i = tid; i < NM * CP; i += THREADS) go[i] = s_acc[i];
}

extern "C" void kernel_launch(void* const* d_in, const int* in_sizes, int n_in,
                              void* d_out, int out_size) {
    const float* x1 = (const float*)d_in[0];
    const float* x2 = (const float*)d_in[1];
    const float* wt = (const float*)d_in[2];
    const float* cg = (const float*)d_in[3];
    const int*   Mo = (const int*)d_in[4];
    const int*   M1 = (const int*)d_in[5];
    const int*   M2 = (const int*)d_in[6];
    const int*   li = (const int*)d_in[7];

    pack_kernel<<<(NNZ_K + 255) / 256, 256>>>(Mo, M1, M2, li, cg);
    tp_kernel<<<B_TOT, THREADS>>>(x1, x2, wt, (float*)d_out);
}

// round 5
// speedup vs baseline: 1.0709x; 1.0709x over previous
#include <cuda_runtime.h>
#include <cstdint>

#define B_TOT   4096
#define NM      25
#define C_CH    64
#define CP      (C_CH / 2)        /* 32 float2 channel-pairs, one per lane */
#define NNZ_K   1000
#define NW      55
#define THREADS 256
#define WARPS   8
#define EPW     (NNZ_K / WARPS)   /* 125 entries per warp */
#define F_REUSE (1u << 21)

// sorted order + packed meta: {M1 | M2<<5 | l_ind<<10 | M_out<<16 | reuse<<21, cg_bits}
__device__ int   g_order[NNZ_K];
__device__ uint2 g_meta[NNZ_K];

// ---- counting sort by key = (M_out<<5 | M1); M_out already globally sorted,
// ---- so result preserves M_out order and clusters equal M1 within segments.
__global__ void __launch_bounds__(1024) sort_kernel(const int* __restrict__ Mo,
                                                    const int* __restrict__ M1) {
    __shared__ int hist[1024];
    __shared__ int tmp[1024];
    const int tid = threadIdx.x;
    hist[tid] = 0;
    __syncthreads();
    int key = -1;
    if (tid < NNZ_K) {
        key = (Mo[tid] << 5) | M1[tid];
        atomicAdd(&hist[key], 1);
    }
    __syncthreads();
    const int cnt = hist[tid];
    int v = cnt;
    #pragma unroll
    for (int d = 1; d < 1024; d <<= 1) {       // Hillis-Steele inclusive scan
        tmp[tid] = v;
        __syncthreads();
        if (tid >= d) v += tmp[tid - d];
        __syncthreads();
    }
    hist[tid] = v - cnt;                        // exclusive base
    __syncthreads();
    if (tid < NNZ_K) {
        int pos = atomicAdd(&hist[key], 1);     // rank within key (order-agnostic)
        g_order[pos] = tid;
    }
}

__global__ void build_kernel(const int* __restrict__ Mo, const int* __restrict__ M1,
                             const int* __restrict__ M2, const int* __restrict__ li,
                             const float* __restrict__ cg) {
    int n = blockIdx.x * blockDim.x + threadIdx.x;
    if (n < NNZ_K) {
        const int i = g_order[n];
        unsigned p = (unsigned)M1[i] | ((unsigned)M2[i] << 5) |
                     ((unsigned)li[i] << 10) | ((unsigned)Mo[i] << 16);
        if ((n % EPW) != 0) {                   // reuse never crosses a warp-chunk boundary
            if (M1[g_order[n - 1]] == M1[i]) p |= F_REUSE;
        }
        g_meta[n] = make_uint2(p, __float_as_uint(cg[i]));
    }
}

__device__ __forceinline__ unsigned sm_u32(const void* p) {
    unsigned r;
    asm("{ .reg .u64 t; cvta.to.shared.u64 t, %1; cvt.u32.u64 %0, t; }" : "=r"(r) : "l"(p));
    return r;
}

__global__ void __launch_bounds__(THREADS) tp_kernel(
    const float* __restrict__ x1, const float* __restrict__ x2,
    const float* __restrict__ wt, float* __restrict__ out)
{
    __shared__ float2 s_x1 [NM * CP];
    __shared__ float2 s_x2 [NM * CP];
    __shared__ float2 s_w  [NW * CP];
    __shared__ float2 s_acc[NM * CP];
    __shared__ float2 s_pv [WARPS * 2 * CP];   // boundary-partial values
    __shared__ uint2  s_meta[NNZ_K];
    __shared__ int    s_pmo[WARPS * 2];        // boundary-partial segment ids

    const int tid = threadIdx.x;
    const int b   = blockIdx.x;

    // ---- stage batch data into shared ----
    const float2* gx1 = (const float2*)(x1 + (size_t)b * NM * C_CH);
    const float2* gx2 = (const float2*)(x2 + (size_t)b * NM * C_CH);
    const float2* gw  = (const float2*)(wt + (size_t)b * NW * C_CH);
    for (int i = tid; i < NM * CP; i += THREADS) {
        s_x1[i] = gx1[i];
        s_x2[i] = gx2[i];
        s_acc[i] = make_float2(0.f, 0.f);
    }
    for (int i = tid; i < NW * CP; i += THREADS) s_w[i] = gw[i];
    for (int i = tid; i < WARPS * 2 * CP; i += THREADS) s_pv[i] = make_float2(0.f, 0.f);
    if (tid < WARPS * 2) s_pmo[tid] = 0;
    for (int i = tid; i < NNZ_K; i += THREADS) s_meta[i] = g_meta[i];
    __syncthreads();

    const int lane = tid & 31;
    const int w    = tid >> 5;
    const unsigned a_x1 = sm_u32(s_x1) + lane * 8;

    // ---- main loop: warp w handles entries [w*EPW, (w+1)*EPW), all 64 channels ----
    int n = w * EPW;
    const int nend = n + EPW;
    int cur = (int)((s_meta[n].x >> 16) & 31u);
    float2 acc = make_float2(0.f, 0.f);
    float  v1x = 0.f, v1y = 0.f;               // register-carried x1 gather
    bool first = true;

    #pragma unroll 4
    for (; n < nend; ++n) {
        const uint2 me = s_meta[n];            // uniform broadcast (1 wavefront)
        const unsigned p = me.x;
        const int mo = (int)((p >> 16) & 31u);
        if (mo != cur) {                       // uniform branch: close segment `cur`
            if (first) {                       // first segment may span a warp boundary
                s_pv[(w * 2) * CP + lane] = acc;
                if (lane == 0) s_pmo[w * 2] = cur;
                first = false;
            } else {                           // interior segment: exclusively owned (M_out sorted)
                s_acc[cur * CP + lane] = acc;
            }
            acc = make_float2(0.f, 0.f);
            cur = mo;
        }
        // predicated x1 gather: skipped (no wavefront, no branch) when reuse flag set
        {
            const unsigned ax = a_x1 + ((p & 31u) << 8);
            asm volatile("{ .reg .pred q; .reg .u32 t;\n\t"
                         "and.b32 t, %3, %4;\n\t"
                         "setp.eq.u32 q, t, 0;\n\t"
                         "@q ld.shared.v2.f32 {%0, %1}, [%2]; }"
                         : "+f"(v1x), "+f"(v1y)
                         : "r"(ax), "r"(p), "n"(F_REUSE));
        }
        const float2 v2 = s_x2[((p >> 5)  & 31u) * CP + lane];
        const float2 vw = s_w [((p >> 10) & 63u) * CP + lane];
        const float  cg = __uint_as_float(me.y);
        acc.x = fmaf(v1x * v2.x, cg * vw.x, acc.x);
        acc.y = fmaf(v1y * v2.y, cg * vw.y, acc.y);
    }
    // final (possibly boundary-spanning) segment -> partial slot
    s_pv[(w * 2 + 1) * CP + lane] = acc;
    if (lane == 0) s_pmo[w * 2 + 1] = cur;
    __syncthreads();

    // ---- merge boundary partials: one warp, lane owns its channel pair -> no races ----
    if (tid < 32) {
        #pragma unroll
        for (int s = 0; s < WARPS * 2; ++s) {
            const int mo = s_pmo[s];
            const float2 v = s_pv[s * CP + lane];
            float2 a = s_acc[mo * CP + lane];
            a.x += v.x; a.y += v.y;
            s_acc[mo * CP + lane] = a;
        }
    }
    __syncthreads();

    // ---- write out ----
    float2* go = (float2*)(out + (size_t)b * NM * C_CH);
    for (int i = tid; i < NM * CP; i += THREADS) go[i] = s_acc[i];
}

extern "C" void kernel_launch(void* const* d_in, const int* in_sizes, int n_in,
                              void* d_out, int out_size) {
    const float* x1 = (const float*)d_in[0];
    const float* x2 = (const float*)d_in[1];
    const float* wt = (const float*)d_in[2];
    const float* cg = (const float*)d_in[3];
    const int*   Mo = (const int*)d_in[4];
    const int*   M1 = (const int*)d_in[5];
    const int*   M2 = (const int*)d_in[6];
    const int*   li = (const int*)d_in[7];

    sort_kernel<<<1, 1024>>>(Mo, M1);
    build_kernel<<<(NNZ_K + 255) / 256, 256>>>(Mo, M1, M2, li, cg);
    tp_kernel<<<B_TOT, THREADS>>>(x1, x2, wt, (float*)d_out);
}